// round 17
// baseline (speedup 1.0000x reference)
#include <cuda_runtime.h>
#include <cuda_bf16.h>
#include <math.h>

#define NN   4096
#define FF   512
#define HH   60
#define CC   4
#define CAP  64      // max nnz per row (mean ~8.2; 64 > 18 sigma)
#define NBLK 148     // persistent grid: <= SM count -> all co-resident

// device globals only (never passed from host — R3 post-mortem)
__device__ int   g_sync[3];          // grid-barrier counters; zeroed by k_reset each replay
__device__ float g_deg[NN];          // zero-init; reset by k_net phase D for replay
__device__ float g_self[NN];
__device__ int   g_cnt[NN];
__device__ int   g_cols[NN * CAP];
__device__ float g_vals[NN * CAP];   // after phase A: fully normalized edge weight
__device__ __align__(16) float g_Ta[NN * HH + 16]; // +16 pad: cl==15 reads cols 60..63 harmlessly
__device__ __align__(16) float g_Tb[NN * HH + 16];

__device__ __forceinline__ void cp16(unsigned s, const void* g) {
    asm volatile("cp.async.cg.shared.global [%0], [%1], 16;\n" :: "r"(s), "l"(g));
}
__device__ __forceinline__ unsigned smaddr(const void* p) {
    return (unsigned)__cvta_generic_to_shared(p);
}

// ---------------------------------------------------------------------------
__global__ void k_reset() { if (threadIdx.x < 3) g_sync[threadIdx.x] = 0; }

// ---------------------------------------------------------------------------
// K1: scan sub_adj (67 MB, HBM floor), warp-ballot edge compaction, P_vec
// gather at nonzeros, sigmoid, column-degree atomic accumulation.
// (ballot here is legal: uniform trip counts, all lanes converged.)
__global__ void k_build(const float* __restrict__ adj, const float* __restrict__ pvec) {
    int warp = (blockIdx.x * blockDim.x + threadIdx.x) >> 5;
    int lane = threadIdx.x & 31;
    if (warp >= NN) return;
    const int row = warp;
    const float4* rp = reinterpret_cast<const float4*>(adj + (size_t)row * NN);
    int cnt = 0;
    #pragma unroll 4
    for (int it = 0; it < NN / 128; ++it) {
        float4 v = rp[it * 32 + lane];
        int jb = it * 128 + lane * 4;
        float vv[4] = {v.x, v.y, v.z, v.w};
        #pragma unroll
        for (int q = 0; q < 4; ++q) {
            bool nz = (vv[q] != 0.0f);
            unsigned m = __ballot_sync(0xffffffffu, nz);
            if (nz) {
                int j = jb + q;
                int slot = cnt + __popc(m & ((1u << lane) - 1u));
                int a = row > j ? row : j;
                int b = row > j ? j : row;
                float p = pvec[(size_t)a * (a + 1) / 2 + b];   // tril idx a(a+1)/2+b
                float s = vv[q] / (1.0f + expf(-p));            // sigmoid(p)*adj
                if (slot < CAP) {
                    g_cols[row * CAP + slot] = j;
                    g_vals[row * CAP + slot] = s;
                }
                atomicAdd(&g_deg[j], s);
            }
            cnt += __popc(m);
        }
    }
    if (lane == 0) g_cnt[row] = cnt < CAP ? cnt : CAP;
}

// ---------------------------------------------------------------------------
// grid barrier: syncthreads -> thread0 {release fence, atomic arrive,
// atomic-read spin, acquire fence (CCTL.IVALL flushes L1D -> later plain
// loads coherent)} -> syncthreads. Deterministic (ordering only).
__device__ __forceinline__ void gbar(int p) {
    __syncthreads();
    if (threadIdx.x == 0) {
        __threadfence();
        atomicAdd(&g_sync[p], 1);
        while (atomicAdd(&g_sync[p], 0) < NBLK) { }
        __threadfence();
    }
    __syncthreads();
}

// shared-memory layout (phase-overlapped union)
#define SB_BYTES 24448

// gather one row-set into hs: warp per row; lane l: sub=l>>4 (2-way edge
// split), cl=l&15 (float4 col chunk; cl==15 reads pad, store-guarded).
// R16 FIX: NO warp shuffles inside the divergent edge loop (that was UB ->
// garbage col -> illegal address). Direct cp[e]/vp[e] scalar loads instead.
// The shfl_down reduction AFTER the loop is legal (single static instr, all
// 32 lanes reconverge there).
template <bool RELU>
__device__ __forceinline__ void gather_rows(const float* __restrict__ Tin,
                                            const float* __restrict__ bias,
                                            float* hs, int roff, int count) {
    int w = threadIdx.x >> 5, l = threadIdx.x & 31;
    int sub = l >> 4, cl = l & 15;
    for (int it = 0; it < 2; ++it) {
        int lr = w + 16 * it;
        if (lr < count) {                       // warp-uniform
            int row = roff + lr;
            int cnt = g_cnt[row];
            const int*   cp = &g_cols[row * CAP];
            const float* vp = &g_vals[row * CAP];
            float4 acc = make_float4(0.f, 0.f, 0.f, 0.f);
            if (sub == 0) {
                float s = g_self[row];
                float4 tv = *(const float4*)&Tin[row * HH + cl * 4];
                acc.x = s * tv.x; acc.y = s * tv.y; acc.z = s * tv.z; acc.w = s * tv.w;
            }
            for (int e = sub; e < cnt; e += 2) {
                int   col = cp[e] & (NN - 1);   // defensive mask: bad data -> wrong value (measurable), not crash
                float wv  = vp[e];
                float4 tv = *(const float4*)&Tin[col * HH + cl * 4];
                acc.x += wv * tv.x; acc.y += wv * tv.y;
                acc.z += wv * tv.z; acc.w += wv * tv.w;
            }
            acc.x += __shfl_down_sync(0xffffffffu, acc.x, 16);
            acc.y += __shfl_down_sync(0xffffffffu, acc.y, 16);
            acc.z += __shfl_down_sync(0xffffffffu, acc.z, 16);
            acc.w += __shfl_down_sync(0xffffffffu, acc.w, 16);
            if (sub == 0 && cl < 15) {
                float4 bb = *(const float4*)&bias[cl * 4];
                float4 r;
                if (RELU) {
                    r.x = fmaxf(acc.x + bb.x, 0.f); r.y = fmaxf(acc.y + bb.y, 0.f);
                    r.z = fmaxf(acc.z + bb.z, 0.f); r.w = fmaxf(acc.w + bb.w, 0.f);
                } else {
                    r.x = acc.x + bb.x; r.y = acc.y + bb.y;
                    r.z = acc.z + bb.z; r.w = acc.w + bb.w;
                }
                *(float4*)&hs[lr * HH + cl * 4] = r;
            }
        }
    }
}

// ---------------------------------------------------------------------------
// Persistent fused net: phase A (norm + x@W1), B (layer1), C (layer2), D (final).
__global__ void __launch_bounds__(512, 1) k_net(
    const float* __restrict__ x,  const float* __restrict__ W1,
    const float* __restrict__ b1, const float* __restrict__ W2,
    const float* __restrict__ b2, const float* __restrict__ W3,
    const float* __restrict__ b3, const float* __restrict__ lw,
    const float* __restrict__ lb, float* __restrict__ out)
{
    __shared__ __align__(16) char sbuf[SB_BYTES];
    float* As = (float*)sbuf;                   // xw: [2][28][36] = 2016 floats
    float* Wx = (float*)(sbuf + 2016 * 4);      // xw: [2][32][64] = 4096 floats
    float* Wd = (float*)sbuf;                   // layer: [60][64] = 3840 floats
    float* hs = (float*)(sbuf + 3840 * 4);      // layer: [28][60] = 1680 floats

    const int tid   = threadIdx.x;
    const int b     = blockIdx.x;
    const int count = (b < 100) ? 28 : 27;
    const int roff  = (b < 100) ? b * 28 : 2800 + (b - 100) * 27;

    // ---- phase A.1: fold D^{-1/2} into own rows' edges ----
    for (int i = tid; i < count * 16; i += 512) {
        int lr = i >> 4, le = i & 15;
        int row = roff + lr;
        float di = rsqrtf(g_deg[row] + 1.0f);
        int cnt = g_cnt[row];
        for (int e = le; e < cnt; e += 16)
            g_vals[row * CAP + e] *= di * rsqrtf(g_deg[g_cols[row * CAP + e]] + 1.0f);
        if (le == 0) g_self[row] = di * di;
    }

    // ---- phase A.2: g_Ta[own rows] = x @ W1 (16 x BK=32 tiles, dbl-buffer) ----
    if (tid < 64) {   // zero Wx pad cols 60..63, both bufs
        int bb = tid >> 5, wk = tid & 31;
        *(float4*)&Wx[bb * 2048 + wk * 64 + 60] = make_float4(0.f, 0.f, 0.f, 0.f);
    }
    __syncthreads();

    const int grp = tid >> 4;      // row (0..31; active < count)
    const int c4  = tid & 15;      // col quad (active < 15)

    auto stage = [&](int tile, int buf) {
        int k0 = tile * 32;
        if (tid < 224) {                               // As: 28 rows x 32 k
            int row = tid >> 3, kk = (tid & 7) * 4;
            if (row < count)
                cp16(smaddr(As + buf * 1008 + row * 36 + kk),
                     x + (size_t)(roff + row) * FF + k0 + kk);
        } else if (tid < 480) {                        // Wx: 32 k x 60 cols
            int u = tid - 224, wk = u >> 3, wc = (u & 7) * 8;
            cp16(smaddr(Wx + buf * 2048 + wk * 64 + wc),
                 W1 + (size_t)(k0 + wk) * HH + wc);
            if (wc + 4 < HH)
                cp16(smaddr(Wx + buf * 2048 + wk * 64 + wc + 4),
                     W1 + (size_t)(k0 + wk) * HH + wc + 4);
        }
        asm volatile("cp.async.commit_group;\n");
    };

    unsigned long long xa0 = 0ull, xa1 = 0ull;   // 4 cols as 2x f32x2
    stage(0, 0);
    int buf = 0;
    for (int tile = 0; tile < 16; ++tile) {
        __syncthreads();
        if (tile < 15) {
            stage(tile + 1, buf ^ 1);
            asm volatile("cp.async.wait_group 1;\n");
        } else {
            asm volatile("cp.async.wait_group 0;\n");
        }
        __syncthreads();
        const float* Ab = As + buf * 1008;
        const float* Wb = Wx + buf * 2048;
        #pragma unroll
        for (int k4 = 0; k4 < 32; k4 += 4) {
            float4 av = *(const float4*)&Ab[grp * 36 + k4];
            #pragma unroll
            for (int j = 0; j < 4; ++j) {
                unsigned a = __float_as_uint((&av.x)[j]);
                unsigned long long pa;
                asm("mov.b64 %0, {%1, %1};" : "=l"(pa) : "r"(a));
                ulonglong2 wv = *(const ulonglong2*)&Wb[(k4 + j) * 64 + 4 * c4];
                asm("fma.rn.f32x2 %0, %1, %2, %0;" : "+l"(xa0) : "l"(pa), "l"(wv.x));
                asm("fma.rn.f32x2 %0, %1, %2, %0;" : "+l"(xa1) : "l"(pa), "l"(wv.y));
            }
        }
        buf ^= 1;
    }
    if (grp < count && c4 < 15) {
        unsigned lo0, hi0, lo1, hi1;
        asm("mov.b64 {%0, %1}, %2;" : "=r"(lo0), "=r"(hi0) : "l"(xa0));
        asm("mov.b64 {%0, %1}, %2;" : "=r"(lo1), "=r"(hi1) : "l"(xa1));
        *(float4*)&g_Ta[(size_t)(roff + grp) * HH + 4 * c4] =
            make_float4(__uint_as_float(lo0), __uint_as_float(hi0),
                        __uint_as_float(lo1), __uint_as_float(hi1));
    }

    gbar(0);

    // ---- phases B, C: fused GCN layers ----
    #pragma unroll 1
    for (int phase = 0; phase < 2; ++phase) {
        const float* Tin  = phase ? g_Tb : g_Ta;
        float*       Tout = phase ? g_Ta : g_Tb;
        const float* bias = phase ? b2 : b1;
        const float* Wn   = phase ? W3 : W2;
        #pragma unroll
        for (int s = 0; s < 2; ++s) {
            int chunk = tid + s * 512;
            if (chunk < 960) {
                int k = chunk >> 4, j = chunk & 15;
                if (j < 15) cp16(smaddr(Wd + k * 64 + j * 4), Wn + k * HH + j * 4);
                else *(float4*)&Wd[k * 64 + 60] = make_float4(0.f, 0.f, 0.f, 0.f);
            }
        }
        asm volatile("cp.async.commit_group;\n");

        gather_rows<true>(Tin, bias, hs, roff, count);

        asm volatile("cp.async.wait_group 0;\n");
        __syncthreads();

        int w = tid >> 5, p = tid & 31;
        for (int half = 0; half < 2; ++half) {
            int lr = w + 16 * half;
            if (lr < count) {
                unsigned long long acc2 = 0ull;
                #pragma unroll
                for (int k = 0; k < HH; ++k) {
                    unsigned h = __float_as_uint(hs[lr * HH + k]);
                    unsigned long long ph;
                    asm("mov.b64 %0, {%1, %1};" : "=l"(ph) : "r"(h));
                    unsigned long long wv = *(const unsigned long long*)&Wd[k * 64 + 2 * p];
                    asm("fma.rn.f32x2 %0, %1, %2, %0;" : "+l"(acc2) : "l"(ph), "l"(wv));
                }
                if (p < 30) {
                    unsigned lo, hi;
                    asm("mov.b64 {%0, %1}, %2;" : "=r"(lo), "=r"(hi) : "l"(acc2));
                    *(float2*)&Tout[(roff + lr) * HH + 2 * p] =
                        make_float2(__uint_as_float(lo), __uint_as_float(hi));
                }
            }
        }
        gbar(phase + 1);
    }

    // ---- phase D: final gather (+b3), logits, log_softmax ----
    gather_rows<false>(g_Ta, b3, hs, roff, count);
    __syncthreads();
    {
        int w = tid >> 5, l = tid & 31;
        for (int half = 0; half < 2; ++half) {
            int lr = w + 16 * half;
            if (lr < count) {                           // warp-uniform
                float p0 = 0.f, p1 = 0.f, p2 = 0.f, p3 = 0.f;
                if (l < 30) {
                    float h0 = hs[lr * HH + 2 * l], h1 = hs[lr * HH + 2 * l + 1];
                    float4 wa = *(const float4*)&lw[(2 * l) * CC];
                    float4 wb = *(const float4*)&lw[(2 * l + 1) * CC];
                    p0 = h0 * wa.x + h1 * wb.x;
                    p1 = h0 * wa.y + h1 * wb.y;
                    p2 = h0 * wa.z + h1 * wb.z;
                    p3 = h0 * wa.w + h1 * wb.w;
                }
                #pragma unroll
                for (int off = 16; off; off >>= 1) {
                    p0 += __shfl_down_sync(0xffffffffu, p0, off);
                    p1 += __shfl_down_sync(0xffffffffu, p1, off);
                    p2 += __shfl_down_sync(0xffffffffu, p2, off);
                    p3 += __shfl_down_sync(0xffffffffu, p3, off);
                }
                if (l == 0) {
                    float lg0 = p0 + lb[0], lg1 = p1 + lb[1];
                    float lg2 = p2 + lb[2], lg3 = p3 + lb[3];
                    float m = fmaxf(fmaxf(lg0, lg1), fmaxf(lg2, lg3));
                    float s = expf(lg0 - m) + expf(lg1 - m) +
                              expf(lg2 - m) + expf(lg3 - m);
                    float ls = m + logf(s);
                    *(float4*)&out[(size_t)(roff + lr) * CC] =
                        make_float4(lg0 - ls, lg1 - ls, lg2 - ls, lg3 - ls);
                }
            }
        }
    }
    // reset g_deg for next graph replay (last read was phase A)
    for (int i = tid; i < count; i += 512) g_deg[roff + i] = 0.0f;
}

// ---------------------------------------------------------------------------
// Inputs resolved BY ELEMENT COUNT; same-size ties by relative order.
extern "C" void kernel_launch(void* const* d_in, const int* in_sizes, int n_in,
                              void* d_out, int out_size) {
    const float *x = 0, *adj = 0, *pvec = 0, *W1 = 0, *b1 = 0, *W2 = 0, *b2 = 0,
                *W3 = 0, *b3 = 0, *lin_w = 0, *lin_b = 0;
    int nb = 0, nw = 0;
    for (int i = 0; i < n_in; ++i) {
        const float* p = (const float*)d_in[i];
        switch (in_sizes[i]) {
            case NN * FF:            x = p;    break;
            case NN * NN:            adj = p;  break;
            case (NN * (NN + 1)) / 2: pvec = p; break;
            case FF * HH:            W1 = p;   break;
            case HH * HH:
                if (nw == 0) W2 = p; else W3 = p;
                ++nw; break;
            case HH:
                if (nb == 0) b1 = p; else if (nb == 1) b2 = p; else b3 = p;
                ++nb; break;
            case HH * CC:            lin_w = p; break;
            case CC:                 lin_b = p; break;
            default: break;
        }
    }
    float* out = (float*)d_out;

    k_build<<<NN / 8, 256>>>(adj, pvec);   // edge lists + degrees (HBM floor)
    k_reset<<<1, 32>>>();                  // zero grid-barrier counters (replay-safe)
    k_net<<<NBLK, 512>>>(x, W1, b1, W2, b2, W3, b3, lin_w, lin_b, out);
}